// round 17
// baseline (speedup 1.0000x reference)
#include <cuda_runtime.h>
#include <cuda_bf16.h>

// HamiltonianFlow: 100 RK4 steps, 400 sequential MLP-gradient evals.
// 128 CTAs x 2 samples, NT=256, software-pipelined fwd(r) || bwd(r-1),
// ONE barrier per region (R14 skeleton).
//
// R17: bf16 weights + fp32 FFMA2 accumulation. bf16 -> fp32 expansion is
// EXACT and conversion-free: lo = w<<16 (SHF), hi = w & 0xffff0000 (LOP3),
// both on the idle ALU pipe -- removes the 512 slow F2F ops/region that
// R14 put through the conversion pipe. Accumulation numerics identical to
// R14 (fp32), weight quantization 8x coarser: predicted rel_err ~6e-4.
//  - forward: all 256 rows in smem hw[j][f] bf16, stride 264 (conflict-free
//    LDS.128 rows), expand -> fma.rn.f32x2.
//  - backward: full row W1[t][:] register-resident as 128 bf16-pair words.

#define STEPS 100
#define DTV   0.01f
#define NT    256
#define NCTA  128
#define NREG  (4 * STEPS + 1)
#define HSTRIDE 264

typedef unsigned long long ull;

#define HW_BYTES (256 * HSTRIDE * 2)              // 135168
#define SMEM_BYTES (HW_BYTES + 2048 * 4)          // + qb/ub fp32 dbl-buf

__device__ __forceinline__ void fma2(ull& d, ull a, ull b) {
    asm("fma.rn.f32x2 %0, %1, %2, %0;" : "+l"(d) : "l"(a), "l"(b));
}
// expand a packed bf16 pair (lo,hi in one u32) to a packed f32x2 (exact)
__device__ __forceinline__ ull bfexp(unsigned w) {
    unsigned lo = w << 16;
    unsigned hi = w & 0xffff0000u;
    ull d;
    asm("mov.b64 %0, {%1, %2};" : "=l"(d) : "r"(lo), "r"(hi));
    return d;
}
__device__ __forceinline__ unsigned pkbf(float x, float y) {
    __nv_bfloat162 b = __floats2bfloat162_rn(x, y);
    return *(unsigned*)&b;
}
__device__ __forceinline__ float psum(ull v) {
    return __uint_as_float((unsigned)(v & 0xffffffffu)) +
           __uint_as_float((unsigned)(v >> 32));
}

__global__ __launch_bounds__(NT, 1)
void hflow_kernel(const float* __restrict__ x0,
                  const float* __restrict__ W1,
                  const float* __restrict__ b1,
                  const float* __restrict__ W2,
                  float* __restrict__ out)
{
    extern __shared__ char smraw[];
    unsigned short* hw = (unsigned short*)smraw;  // [256 j][HSTRIDE f] bf16
    float* qb = (float*)(smraw + HW_BYTES);       // [2 buf][2 samp][256]
    float* ub = qb + 1024;                        // [2 buf][2 samp][256]

    const int t = threadIdx.x;

    // ---- stage bf16 transposed weights: hw[j*HSTRIDE + f] = W1[f][j] ----
    for (int idx = t; idx < 65536; idx += NT) {
        int f = idx >> 8, j = idx & 255;
        __nv_bfloat16 b = __float2bfloat16_rn(W1[idx]);
        hw[j * HSTRIDE + f] = *(unsigned short*)&b;
    }

    // ---- backward register cache: full row W1[t][:] as 128 bf16 pairs ----
    unsigned rc[128];
    {
        const float4* wr = (const float4*)(W1 + t * 256);
#pragma unroll
        for (int m = 0; m < 64; m++) {
            float4 v = __ldg(wr + m);
            rc[2 * m]     = pkbf(v.x, v.y);
            rc[2 * m + 1] = pkbf(v.z, v.w);
        }
    }

    const float rb1 = b1[t];
    const float rw2 = W2[t];

    const int s0 = blockIdx.x * 2;
    float2 st0 = ((const float2*)x0)[s0 * 256 + t];
    float2 st1 = ((const float2*)x0)[(s0 + 1) * 256 + t];
    float q0[2], p0[2], Aq[2], Ap[2], pc[2];
    q0[0] = st0.x; p0[0] = st0.y;
    q0[1] = st1.x; p0[1] = st1.y;
    Ap[0] = Ap[1] = 0.f;

    qb[t]       = q0[0];                          // stage-0 q into buf 0
    qb[256 + t] = q0[1];
    __syncthreads();

    const unsigned short* wrow = hw + t * HSTRIDE;
    const float h2 = 0.5f * DTV;
    const float d6 = DTV / 6.f;

    for (int r = 0; r < NREG; r++) {
        const int par = r & 1;
        const float* qc = qb + par * 512;
        float*       qn = qb + (par ^ 1) * 512;
        float*       un = ub + par * 512;
        const float* uc = ub + (par ^ 1) * 512;
        const bool has_f = (r < NREG - 1);
        const bool has_b = (r > 0);
        const int sf = r & 3;
        const float cq = (sf == 2) ? DTV : h2;    // c[sf+1]

        // ---- forward: z_t = sum_f q_f * W1[f][t] (stage r) ----
        if (has_f) {
            ull zA0 = 0, zA1 = 0, zB0 = 0, zB1 = 0;
#pragma unroll 8
            for (int f = 0; f < 256; f += 8) {
                uint4 wv = *(const uint4*)(wrow + f);     // 8 bf16 weights
                ulonglong2 qa0 = *(const ulonglong2*)&qc[f];
                ulonglong2 qa1 = *(const ulonglong2*)&qc[f + 4];
                ulonglong2 qx0 = *(const ulonglong2*)&qc[256 + f];
                ulonglong2 qx1 = *(const ulonglong2*)&qc[256 + f + 4];
                ull W0p = bfexp(wv.x);
                ull W1p = bfexp(wv.y);
                ull W2p = bfexp(wv.z);
                ull W3p = bfexp(wv.w);
                fma2(zA0, W0p, qa0.x); fma2(zA1, W1p, qa0.y);
                fma2(zA0, W2p, qa1.x); fma2(zA1, W3p, qa1.y);
                fma2(zB0, W0p, qx0.x); fma2(zB1, W1p, qx0.y);
                fma2(zB0, W2p, qx1.x); fma2(zB1, W3p, qx1.y);
            }
            float z0 = psum(zA0) + psum(zA1) + rb1;
            float z1 = psum(zB0) + psum(zB1) + rb1;
            float e0 = __expf(2.f * z0);
            float e1 = __expf(2.f * z1);
            float th0 = 1.f - 2.f / (e0 + 1.f);
            float th1 = 1.f - 2.f / (e1 + 1.f);
            un[t]       = rw2 * (1.f - th0 * th0);
            un[256 + t] = rw2 * (1.f - th1 * th1);
        }

        // ---- backward: F_t = sum_j W1[t][j] * u_j (stage r-1), all regs ----
        if (has_b) {
            ull fA0 = 0, fA1 = 0, fB0 = 0, fB1 = 0;
#pragma unroll
            for (int k = 0; k < 128; k += 2) {    // j = 2k .. 2k+3
                ulonglong2 u0 = *(const ulonglong2*)&uc[2 * k];
                ulonglong2 u1 = *(const ulonglong2*)&uc[256 + 2 * k];
                ull WA = bfexp(rc[k]);
                ull WB = bfexp(rc[k + 1]);
                fma2(fA0, WA, u0.x); fma2(fA1, WB, u0.y);
                fma2(fB0, WA, u1.x); fma2(fB1, WB, u1.y);
            }
            float F[2];
            F[0] = psum(fA0) + psum(fA1);
            F[1] = psum(fB0) + psum(fB1);

            const int sb = (r - 1) & 3;
            if (sb == 3) {
#pragma unroll
                for (int m = 0; m < 2; m++) {
                    Ap[m] += F[m];
                    p0[m] -= d6 * Ap[m];
                    Ap[m] = 0.f;
                    pc[m] = p0[m];
                    Aq[m] = pc[m];
                }
            } else {
                const float wb_ = (sb == 0) ? 1.f : 2.f;
                const float cn  = (sb == 2) ? DTV : h2;
                const float wn  = (sb == 2) ? 1.f : 2.f;
#pragma unroll
                for (int m = 0; m < 2; m++) {
                    Ap[m] += wb_ * F[m];
                    pc[m] = p0[m] - cn * F[m];
                    Aq[m] += wn * pc[m];
                }
            }
            if (has_f) {
                if (sf == 3) {
                    q0[0] += d6 * Aq[0];
                    q0[1] += d6 * Aq[1];
                    qn[t]       = q0[0];
                    qn[256 + t] = q0[1];
                } else {
                    qn[t]       = q0[0] + cq * pc[0];
                    qn[256 + t] = q0[1] + cq * pc[1];
                }
            }
        } else {
            // r == 0: stage 0
            pc[0] = p0[0]; Aq[0] = pc[0];
            pc[1] = p0[1]; Aq[1] = pc[1];
            qn[t]       = q0[0] + cq * pc[0];
            qn[256 + t] = q0[1] + cq * pc[1];
        }

        __syncthreads();                          // single barrier per region
    }

    ((float2*)out)[s0 * 256 + t]       = make_float2(q0[0], p0[0]);
    ((float2*)out)[(s0 + 1) * 256 + t] = make_float2(q0[1], p0[1]);
}

extern "C" void kernel_launch(void* const* d_in, const int* in_sizes, int n_in,
                              void* d_out, int out_size) {
    const float* x0 = (const float*)d_in[0];
    const float* W1 = (const float*)d_in[1];
    const float* b1 = (const float*)d_in[2];
    const float* W2 = (const float*)d_in[3];
    cudaFuncSetAttribute(hflow_kernel,
                         cudaFuncAttributeMaxDynamicSharedMemorySize, SMEM_BYTES);
    hflow_kernel<<<NCTA, NT, SMEM_BYTES>>>(x0, W1, b1, W2, (float*)d_out);
}